// round 1
// baseline (speedup 1.0000x reference)
#include <cuda_runtime.h>

#define TT 1024
#define KK 64
#define DD 256
#define NT (TT*KK)          // 65536 (t,k) rows
#define NE ((TT-1)*KK*KK)   // 1023 * 4096 transition-exp entries

// ---- device scratch (static allocation only; no cudaMalloc allowed) ----
__device__ float g_we_e0[DD], g_we_e1[DD], g_wt0[DD], g_wt1[DD];
__device__ float g_ce, g_ct;
__device__ float g_obsdot[TT];
__device__ float g_u[NT], g_v[NT], g_emit[NT];
__device__ float g_E[NE];   // layout [t][k_cur][j_prev], 16.8 MB (L2-resident)

// ============================================================
// K0: fold conv+linear into effective weight vectors + constants
//   weff[d] = w0*lw[d+1] + w1*lw[d] + w2*lw[d-1]   (lw out of range = 0)
//   c = conv_b * sum(lw) + lin_b
// ============================================================
__global__ void prep_kernel(const float* __restrict__ ecw, const float* __restrict__ ecb,
                            const float* __restrict__ elw, const float* __restrict__ elb,
                            const float* __restrict__ tcw, const float* __restrict__ tcb,
                            const float* __restrict__ tlw, const float* __restrict__ tlb)
{
    int d = threadIdx.x;  // 256 threads
    float em1 = (d > 0)      ? elw[d-1] : 0.f;
    float e0  = elw[d];
    float ep1 = (d < DD-1)   ? elw[d+1] : 0.f;
    g_we_e0[d] = ecw[0]*ep1 + ecw[1]*e0 + ecw[2]*em1;   // channel 0 (obs)
    g_we_e1[d] = ecw[3]*ep1 + ecw[4]*e0 + ecw[5]*em1;   // channel 1 (cand)

    float tm1 = (d > 0)      ? tlw[d-1] : 0.f;
    float t0  = tlw[d];
    float tp1 = (d < DD-1)   ? tlw[d+1] : 0.f;
    g_wt0[d]  = tcw[0]*tp1 + tcw[1]*t0 + tcw[2]*tm1;    // prev term (u)
    g_wt1[d]  = tcw[3]*tp1 + tcw[4]*t0 + tcw[5]*tm1;    // cur  term (v)

    __shared__ float se[8], st[8];
    float ve = e0, vt = t0;
    #pragma unroll
    for (int o = 16; o; o >>= 1) {
        ve += __shfl_xor_sync(0xffffffffu, ve, o);
        vt += __shfl_xor_sync(0xffffffffu, vt, o);
    }
    if ((d & 31) == 0) { se[d >> 5] = ve; st[d >> 5] = vt; }
    __syncthreads();
    if (d == 0) {
        float Se = 0.f, St = 0.f;
        #pragma unroll
        for (int i = 0; i < 8; i++) { Se += se[i]; St += st[i]; }
        g_ce = ecb[0] * Se + elb[0];
        g_ct = tcb[0] * St + tlb[0];
    }
}

// ============================================================
// K1: obsdot[t] = obs_t . we_e0   (one warp per t)
// ============================================================
__global__ void obsdot_kernel(const float* __restrict__ obs)
{
    int gw   = (blockIdx.x * blockDim.x + threadIdx.x) >> 5;
    int lane = threadIdx.x & 31;
    if (gw >= TT) return;
    const float4* o4 = (const float4*)(obs + (size_t)gw * DD);
    const float4* w4 = (const float4*)g_we_e0;
    float s = 0.f;
    #pragma unroll
    for (int q = 0; q < 2; q++) {
        int i = lane * 2 + q;
        float4 a = o4[i], b = w4[i];
        s += a.x*b.x + a.y*b.y + a.z*b.z + a.w*b.w;
    }
    #pragma unroll
    for (int o = 16; o; o >>= 1) s += __shfl_xor_sync(0xffffffffu, s, o);
    if (lane == 0) g_obsdot[gw] = s;
}

// ============================================================
// K2: embedding gather + 3 effective dots per (t,k) row (one warp/row)
//     emit = sigmoid(obsdot[t] + cand.we_e1 + c_e); u = cand.wt0; v = cand.wt1
// ============================================================
__global__ void gather_kernel(const int* __restrict__ cids, const float* __restrict__ emb)
{
    int r    = (blockIdx.x * blockDim.x + threadIdx.x) >> 5;
    int lane = threadIdx.x & 31;
    if (r >= NT) return;
    int cid = __ldg(cids + r);
    const float4* e4  = (const float4*)(emb + (size_t)cid * DD);
    const float4* we1 = (const float4*)g_we_e1;
    const float4* wt0 = (const float4*)g_wt0;
    const float4* wt1 = (const float4*)g_wt1;
    float de = 0.f, du = 0.f, dv = 0.f;
    #pragma unroll
    for (int q = 0; q < 2; q++) {
        int i = lane * 2 + q;
        float4 x = e4[i];
        float4 a = we1[i], b = wt0[i], c = wt1[i];
        de = fmaf(x.x, a.x, fmaf(x.y, a.y, fmaf(x.z, a.z, fmaf(x.w, a.w, de))));
        du = fmaf(x.x, b.x, fmaf(x.y, b.y, fmaf(x.z, b.z, fmaf(x.w, b.w, du))));
        dv = fmaf(x.x, c.x, fmaf(x.y, c.y, fmaf(x.z, c.z, fmaf(x.w, c.w, dv))));
    }
    #pragma unroll
    for (int o = 16; o; o >>= 1) {
        de += __shfl_xor_sync(0xffffffffu, de, o);
        du += __shfl_xor_sync(0xffffffffu, du, o);
        dv += __shfl_xor_sync(0xffffffffu, dv, o);
    }
    if (lane == 0) {
        int t = r >> 6;
        float x = de + g_obsdot[t] + g_ce;
        g_emit[r] = 1.f / (1.f + __expf(-x));
        g_u[r] = du;
        g_v[r] = dv;
    }
}

// ============================================================
// K3: E[t][k][j] = exp(sigmoid(u[t][j] + v[t+1][k] + c_t))
// ============================================================
__global__ void ekernel()
{
    int idx = blockIdx.x * blockDim.x + threadIdx.x;
    if (idx >= NE) return;
    int t = idx >> 12;
    int k = (idx >> 6) & 63;
    int j = idx & 63;
    float x = g_u[t * 64 + j] + g_v[(t + 1) * 64 + k] + g_ct;
    float s = 1.f / (1.f + __expf(-x));
    g_E[idx] = __expf(s);
}

// ============================================================
// K4: sequential CRF forward DP. Single block, 64 threads.
// Thread k owns column k. Per step:
//   a_j = exp(alpha_j - S)  (S = lagged exact max, uniform)
//   alpha'_k = log( sum_j a_j * E[t][k][j] ) + S + emit[t+1][k]
// E rows register-double-buffered (prefetch hides L2 latency).
// Lagged max: wmax ping-pong buffers; shift lag <= 2 steps keeps
// exp args in [-2, ~12.3] (growth/step bounded by 2 + ln 64).
// ============================================================
__device__ __forceinline__ void dp_iter(int i, float& alpha, float& S, float& emit_cur,
                                        float4 (&Ec)[16], float4 (&En)[16],
                                        float4* a_sh, float (*wmax)[2],
                                        int k, int w, int lane,
                                        const float4* Ebase)
{
    // 1) exponentiate under current shift, publish to smem
    float e = __expf(alpha - S);
    ((float*)a_sh)[k] = e;
    __syncthreads();                          // a_sh ready; prev-iter wmax ready

    float Snew = fmaxf(wmax[i & 1][0], wmax[i & 1][1]);

    // 2) prefetch next E row + next emit (latency hidden by dot below)
    int ip = (i + 1 < TT - 1) ? (i + 1) : (TT - 2);
    #pragma unroll
    for (int q = 0; q < 16; q++) En[q] = Ebase[ip * 1024 + k * 16 + q];
    float emit_next = g_emit[(ip + 1) * 64 + k];

    // 3) lagged max of incoming alpha (off critical path)
    float m = alpha;
    #pragma unroll
    for (int o = 16; o; o >>= 1) m = fmaxf(m, __shfl_xor_sync(0xffffffffu, m, o));
    if (lane == 0) wmax[(i + 1) & 1][w] = m;

    // 4) 64-wide dot: a (smem broadcast) x E (registers), 4 accumulators
    float s0 = 0.f, s1 = 0.f, s2 = 0.f, s3 = 0.f;
    #pragma unroll
    for (int q = 0; q < 16; q++) {
        float4 av = a_sh[q];
        float4 ev = Ec[q];
        s0 = fmaf(av.x, ev.x, s0);
        s1 = fmaf(av.y, ev.y, s1);
        s2 = fmaf(av.z, ev.z, s2);
        s3 = fmaf(av.w, ev.w, s3);
    }
    float sum = (s0 + s1) + (s2 + s3);

    alpha = __logf(sum) + S + emit_cur;
    S = Snew;
    emit_cur = emit_next;
    __syncthreads();                          // protect a_sh reuse
}

__global__ __launch_bounds__(64, 1) void dp_kernel(float* __restrict__ out)
{
    int k = threadIdx.x;          // 0..63 : column ownership
    int w = k >> 5, lane = k & 31;

    __shared__ float4 a_sh[16];
    __shared__ float  wmax[2][2];
    __shared__ float  ssum[2];

    if (k < 2) wmax[0][k] = 0.f;  // shift for iters 0/1 = 0 (alpha_0 in (0,1))

    float alpha = g_emit[k];       // alpha_0 = emit[0]
    float S = 0.f;
    float emit_cur = g_emit[64 + k];

    const float4* Ebase = (const float4*)g_E;
    float4 Ea[16], Eb[16];
    #pragma unroll
    for (int q = 0; q < 16; q++) Ea[q] = Ebase[k * 16 + q];  // E row for iter 0

    // 1023 iterations: 511 unrolled pairs + 1 tail
    for (int i = 0; i < TT - 2; i += 2) {
        dp_iter(i,     alpha, S, emit_cur, Ea, Eb, a_sh, wmax, k, w, lane, Ebase);
        dp_iter(i + 1, alpha, S, emit_cur, Eb, Ea, a_sh, wmax, k, w, lane, Ebase);
    }
    dp_iter(TT - 2, alpha, S, emit_cur, Ea, Eb, a_sh, wmax, k, w, lane, Ebase);

    // final logsumexp over 64 alphas
    float e = __expf(alpha - S);
    #pragma unroll
    for (int o = 16; o; o >>= 1) e += __shfl_xor_sync(0xffffffffu, e, o);
    if (lane == 0) ssum[w] = e;
    __syncthreads();
    if (k == 0) out[0] = __logf(ssum[0] + ssum[1]) + S;
}

// ============================================================
extern "C" void kernel_launch(void* const* d_in, const int* in_sizes, int n_in,
                              void* d_out, int out_size)
{
    const float* obs = (const float*)d_in[0];
    const int*   cid = (const int*)  d_in[1];
    const float* emb = (const float*)d_in[2];
    const float* ecw = (const float*)d_in[3];
    const float* ecb = (const float*)d_in[4];
    const float* elw = (const float*)d_in[5];
    const float* elb = (const float*)d_in[6];
    const float* tcw = (const float*)d_in[7];
    const float* tcb = (const float*)d_in[8];
    const float* tlw = (const float*)d_in[9];
    const float* tlb = (const float*)d_in[10];
    float* out = (float*)d_out;

    prep_kernel<<<1, 256>>>(ecw, ecb, elw, elb, tcw, tcb, tlw, tlb);
    obsdot_kernel<<<TT / 8, 256>>>(obs);          // 1024 warps, 8/block
    gather_kernel<<<NT / 8, 256>>>(cid, emb);     // 65536 warps, 8/block
    ekernel<<<(NE + 255) / 256, 256>>>();
    dp_kernel<<<1, 64>>>(out);
}

// round 2
// speedup vs baseline: 9.3249x; 9.3249x over previous
#include <cuda_runtime.h>

#define TT 1024
#define KK 64
#define DD 256
#define NT (TT*KK)          // 65536 (t,k) rows

// ---- device scratch (static allocation only; no cudaMalloc allowed) ----
__device__ float g_we_e0[DD], g_we_e1[DD], g_wt0[DD], g_wt1[DD];
__device__ float g_ce, g_ct;
__device__ float g_obsdot[TT];
__device__ float g_u[NT], g_v[NT], g_emit[NT];

// tree buffers: ping (A) holds leaves / odd-level outputs, pong (B) even-level outputs
__device__ float g_bufA[1024 * 4096];   // 16.8 MB
__device__ float g_bufB[512 * 4096];    //  8.4 MB
__device__ float g_scA[1024];
__device__ float g_scB[512];

// ============================================================
// K0: fold conv+linear into effective weight vectors + constants
// ============================================================
__global__ void prep_kernel(const float* __restrict__ ecw, const float* __restrict__ ecb,
                            const float* __restrict__ elw, const float* __restrict__ elb,
                            const float* __restrict__ tcw, const float* __restrict__ tcb,
                            const float* __restrict__ tlw, const float* __restrict__ tlb)
{
    int d = threadIdx.x;  // 256 threads
    float em1 = (d > 0)      ? elw[d-1] : 0.f;
    float e0  = elw[d];
    float ep1 = (d < DD-1)   ? elw[d+1] : 0.f;
    g_we_e0[d] = ecw[0]*ep1 + ecw[1]*e0 + ecw[2]*em1;   // channel 0 (obs)
    g_we_e1[d] = ecw[3]*ep1 + ecw[4]*e0 + ecw[5]*em1;   // channel 1 (cand)

    float tm1 = (d > 0)      ? tlw[d-1] : 0.f;
    float t0  = tlw[d];
    float tp1 = (d < DD-1)   ? tlw[d+1] : 0.f;
    g_wt0[d]  = tcw[0]*tp1 + tcw[1]*t0 + tcw[2]*tm1;    // prev term (u)
    g_wt1[d]  = tcw[3]*tp1 + tcw[4]*t0 + tcw[5]*tm1;    // cur  term (v)

    __shared__ float se[8], st[8];
    float ve = e0, vt = t0;
    #pragma unroll
    for (int o = 16; o; o >>= 1) {
        ve += __shfl_xor_sync(0xffffffffu, ve, o);
        vt += __shfl_xor_sync(0xffffffffu, vt, o);
    }
    if ((d & 31) == 0) { se[d >> 5] = ve; st[d >> 5] = vt; }
    __syncthreads();
    if (d == 0) {
        float Se = 0.f, St = 0.f;
        #pragma unroll
        for (int i = 0; i < 8; i++) { Se += se[i]; St += st[i]; }
        g_ce = ecb[0] * Se + elb[0];
        g_ct = tcb[0] * St + tlb[0];
    }
}

// ============================================================
// K1: obsdot[t] = obs_t . we_e0   (one warp per t)
// ============================================================
__global__ void obsdot_kernel(const float* __restrict__ obs)
{
    int gw   = (blockIdx.x * blockDim.x + threadIdx.x) >> 5;
    int lane = threadIdx.x & 31;
    if (gw >= TT) return;
    const float4* o4 = (const float4*)(obs + (size_t)gw * DD);
    const float4* w4 = (const float4*)g_we_e0;
    float s = 0.f;
    #pragma unroll
    for (int q = 0; q < 2; q++) {
        int i = lane * 2 + q;
        float4 a = o4[i], b = w4[i];
        s += a.x*b.x + a.y*b.y + a.z*b.z + a.w*b.w;
    }
    #pragma unroll
    for (int o = 16; o; o >>= 1) s += __shfl_xor_sync(0xffffffffu, s, o);
    if (lane == 0) g_obsdot[gw] = s;
}

// ============================================================
// K2: embedding gather + 3 effective dots per (t,k) row (one warp/row)
// ============================================================
__global__ void gather_kernel(const int* __restrict__ cids, const float* __restrict__ emb)
{
    int r    = (blockIdx.x * blockDim.x + threadIdx.x) >> 5;
    int lane = threadIdx.x & 31;
    if (r >= NT) return;
    int cid = __ldg(cids + r);
    const float4* e4  = (const float4*)(emb + (size_t)cid * DD);
    const float4* we1 = (const float4*)g_we_e1;
    const float4* wt0 = (const float4*)g_wt0;
    const float4* wt1 = (const float4*)g_wt1;
    float de = 0.f, du = 0.f, dv = 0.f;
    #pragma unroll
    for (int q = 0; q < 2; q++) {
        int i = lane * 2 + q;
        float4 x = e4[i];
        float4 a = we1[i], b = wt0[i], c = wt1[i];
        de = fmaf(x.x, a.x, fmaf(x.y, a.y, fmaf(x.z, a.z, fmaf(x.w, a.w, de))));
        du = fmaf(x.x, b.x, fmaf(x.y, b.y, fmaf(x.z, b.z, fmaf(x.w, b.w, du))));
        dv = fmaf(x.x, c.x, fmaf(x.y, c.y, fmaf(x.z, c.z, fmaf(x.w, c.w, dv))));
    }
    #pragma unroll
    for (int o = 16; o; o >>= 1) {
        de += __shfl_xor_sync(0xffffffffu, de, o);
        du += __shfl_xor_sync(0xffffffffu, du, o);
        dv += __shfl_xor_sync(0xffffffffu, dv, o);
    }
    if (lane == 0) {
        int t = r >> 6;
        float x = de + g_obsdot[t] + g_ce;
        g_emit[r] = 1.f / (1.f + __expf(-x));
        g_u[r] = du;
        g_v[r] = dv;
    }
}

// ============================================================
// K3: build 1024 leaf matrices (linear-domain transition factors)
//   t < 1023:  M_t[j][k] = exp( sigmoid(u[t][j]+v[t+1][k]+ct)
//                               + emit[t+1][k] + (t==0 ? emit[0][j] : 0) )
//   t == 1023: identity (padding).  scale[t] = 0.
// ============================================================
__global__ void build_leaves()
{
    int t = blockIdx.x;              // 0..1023
    int tid = threadIdx.x;           // 256
    float* M = g_bufA + (size_t)t * 4096;

    if (t == TT - 1) {               // identity pad
        #pragma unroll
        for (int i = 0; i < 16; i++) {
            int idx = tid + i * 256;
            int j = idx >> 6, k = idx & 63;
            M[idx] = (j == k) ? 1.f : 0.f;
        }
        if (tid == 0) g_scA[t] = 0.f;
        return;
    }

    __shared__ float u_s[64], v_s[64], em_s[64], e0_s[64];
    if (tid < 64) {
        u_s[tid]  = g_u[t * 64 + tid];
        v_s[tid]  = g_v[(t + 1) * 64 + tid];
        em_s[tid] = g_emit[(t + 1) * 64 + tid];
        e0_s[tid] = (t == 0) ? g_emit[tid] : 0.f;
    }
    __syncthreads();
    float ct = g_ct;
    #pragma unroll
    for (int i = 0; i < 16; i++) {
        int idx = tid + i * 256;
        int j = idx >> 6, k = idx & 63;
        float x = u_s[j] + v_s[k] + ct;
        float s = 1.f / (1.f + __expf(-x));
        M[idx] = __expf(s + em_s[k] + e0_s[j]);
    }
    if (tid == 0) g_scA[t] = 0.f;
}

// ============================================================
// K4: one tree level. Block b: out[b] = in[2b] * in[2b+1], rescaled by max.
//   scOut[b] = scIn[2b] + scIn[2b+1] + log(max)
// 128 threads; thread (tx=tid&15, ty=tid>>4) computes C[ty*8+r][tx*4+c].
// ============================================================
__global__ __launch_bounds__(128) void matprod(int lvl)
{
    const float* in  = (lvl & 1) ? g_bufB : g_bufA;
    float*       out = (lvl & 1) ? g_bufA : g_bufB;
    const float* sIn = (lvl & 1) ? g_scB  : g_scA;
    float*       sOut= (lvl & 1) ? g_scA  : g_scB;

    int b = blockIdx.x;
    const float4* A4 = (const float4*)(in + (size_t)(2 * b) * 4096);
    const float4* B4 = A4 + 1024;

    __shared__ float  As[64 * 65];   // row-padded: bank(j*65+m) = (j+m)&31
    __shared__ float4 Bs4[64 * 16];

    int tid = threadIdx.x;
    #pragma unroll
    for (int g = 0; g < 8; g++) {
        int p = tid + g * 128;
        float4 a = A4[p];
        int j = p >> 4, m4 = (p & 15) << 2;
        As[j * 65 + m4 + 0] = a.x;
        As[j * 65 + m4 + 1] = a.y;
        As[j * 65 + m4 + 2] = a.z;
        As[j * 65 + m4 + 3] = a.w;
        Bs4[p] = B4[p];
    }
    __syncthreads();

    int tx = tid & 15, ty = tid >> 4;
    const float* Ab = As + (size_t)ty * 8 * 65;

    float acc[8][4];
    #pragma unroll
    for (int r = 0; r < 8; r++)
        #pragma unroll
        for (int c = 0; c < 4; c++) acc[r][c] = 0.f;

    #pragma unroll 4
    for (int m = 0; m < 64; m++) {
        float4 bv = Bs4[m * 16 + tx];
        #pragma unroll
        for (int r = 0; r < 8; r++) {
            float av = Ab[r * 65 + m];
            acc[r][0] = fmaf(av, bv.x, acc[r][0]);
            acc[r][1] = fmaf(av, bv.y, acc[r][1]);
            acc[r][2] = fmaf(av, bv.z, acc[r][2]);
            acc[r][3] = fmaf(av, bv.w, acc[r][3]);
        }
    }

    // block max
    float mx = acc[0][0];
    #pragma unroll
    for (int r = 0; r < 8; r++)
        #pragma unroll
        for (int c = 0; c < 4; c++) mx = fmaxf(mx, acc[r][c]);
    #pragma unroll
    for (int o = 16; o; o >>= 1) mx = fmaxf(mx, __shfl_xor_sync(0xffffffffu, mx, o));
    __shared__ float wm[4];
    if ((tid & 31) == 0) wm[tid >> 5] = mx;
    __syncthreads();
    float bm = fmaxf(fmaxf(wm[0], wm[1]), fmaxf(wm[2], wm[3]));
    float inv = 1.f / bm;

    float4* O4 = (float4*)(out + (size_t)b * 4096);
    #pragma unroll
    for (int r = 0; r < 8; r++)
        O4[(ty * 8 + r) * 16 + tx] =
            make_float4(acc[r][0] * inv, acc[r][1] * inv, acc[r][2] * inv, acc[r][3] * inv);

    if (tid == 0) sOut[b] = sIn[2 * b] + sIn[2 * b + 1] + logf(bm);
}

// ============================================================
// K5: logZ = log(sum of root entries) + root scale
// root lives in g_bufA[0..4095] (level 9 output), scale in g_scA[0]
// ============================================================
__global__ void final_kernel(float* __restrict__ out)
{
    int tid = threadIdx.x;   // 128
    float s = 0.f;
    #pragma unroll
    for (int i = 0; i < 32; i++) s += g_bufA[tid + i * 128];
    #pragma unroll
    for (int o = 16; o; o >>= 1) s += __shfl_xor_sync(0xffffffffu, s, o);
    __shared__ float ws[4];
    if ((tid & 31) == 0) ws[tid >> 5] = s;
    __syncthreads();
    if (tid == 0)
        out[0] = logf(ws[0] + ws[1] + ws[2] + ws[3]) + g_scA[0];
}

// ============================================================
extern "C" void kernel_launch(void* const* d_in, const int* in_sizes, int n_in,
                              void* d_out, int out_size)
{
    const float* obs = (const float*)d_in[0];
    const int*   cid = (const int*)  d_in[1];
    const float* emb = (const float*)d_in[2];
    const float* ecw = (const float*)d_in[3];
    const float* ecb = (const float*)d_in[4];
    const float* elw = (const float*)d_in[5];
    const float* elb = (const float*)d_in[6];
    const float* tcw = (const float*)d_in[7];
    const float* tcb = (const float*)d_in[8];
    const float* tlw = (const float*)d_in[9];
    const float* tlb = (const float*)d_in[10];
    float* out = (float*)d_out;

    prep_kernel<<<1, 256>>>(ecw, ecb, elw, elb, tcw, tcb, tlw, tlb);
    obsdot_kernel<<<TT / 8, 256>>>(obs);          // 1024 warps, 8/block
    gather_kernel<<<NT / 8, 256>>>(cid, emb);     // 65536 warps, 8/block
    build_leaves<<<TT, 256>>>();

    int cnt = 512;
    for (int lvl = 0; lvl < 10; lvl++) {          // 1024 -> 1 pairwise tree
        matprod<<<cnt, 128>>>(lvl);
        cnt >>= 1;
    }
    final_kernel<<<1, 128>>>(out);
}

// round 3
// speedup vs baseline: 9.3559x; 1.0033x over previous
#include <cuda_runtime.h>

#define TT 1024
#define NT (TT*64)

// ---- device scratch (static only) ----
__device__ float g_u[NT], g_v[NT], g_emit[NT];
__device__ float g_bufA[256 * 4096];   // 4.2 MB
__device__ float g_bufB[256 * 4096];   // 4.2 MB
__device__ float g_scA[256], g_scB[256];
__device__ volatile unsigned g_cnt[8];

// ============================================================
// K1: gather + folded prep + folded obsdot (+ barrier counter reset)
// Block = 8 warps = 8 rows, all sharing one t ( (8b..8b+7)>>6 const ).
// ============================================================
__global__ __launch_bounds__(256) void gather_kernel(
    const int* __restrict__ cids, const float* __restrict__ emb,
    const float* __restrict__ obs,
    const float* __restrict__ ecw, const float* __restrict__ ecb,
    const float* __restrict__ elw, const float* __restrict__ elb,
    const float* __restrict__ tcw, const float* __restrict__ tlw)
{
    __shared__ __align__(16) float we1[256], wt0s[256], wt1s[256];
    __shared__ float redA[8], redB[8];
    __shared__ float s_obsdot, s_ce;

    int tid = threadIdx.x, b = blockIdx.x;
    if (b == 0 && tid < 8) g_cnt[tid] = 0;     // reset tail barriers each replay
    int t = b >> 3;

    // effective weights (prep folded, per-block recompute)
    int d = tid;
    float em1 = (d > 0)   ? elw[d-1] : 0.f;
    float e0v = elw[d];
    float ep1 = (d < 255) ? elw[d+1] : 0.f;
    float we0 = ecw[0]*ep1 + ecw[1]*e0v + ecw[2]*em1;   // obs channel (reg only)
    we1[d]    = ecw[3]*ep1 + ecw[4]*e0v + ecw[5]*em1;
    float tm1 = (d > 0)   ? tlw[d-1] : 0.f;
    float t0v = tlw[d];
    float tp1 = (d < 255) ? tlw[d+1] : 0.f;
    wt0s[d]   = tcw[0]*tp1 + tcw[1]*t0v + tcw[2]*tm1;
    wt1s[d]   = tcw[3]*tp1 + tcw[4]*t0v + tcw[5]*tm1;

    // reductions: sum(elw) for c_e;  obs[t] . we0 for obsdot
    float vsum = e0v;
    float osum = obs[t * 256 + d] * we0;
    #pragma unroll
    for (int o = 16; o; o >>= 1) {
        vsum += __shfl_xor_sync(0xffffffffu, vsum, o);
        osum += __shfl_xor_sync(0xffffffffu, osum, o);
    }
    if ((tid & 31) == 0) { redA[tid >> 5] = vsum; redB[tid >> 5] = osum; }
    __syncthreads();
    if (tid == 0) {
        float sa = 0.f, sb = 0.f;
        #pragma unroll
        for (int i = 0; i < 8; i++) { sa += redA[i]; sb += redB[i]; }
        s_ce = ecb[0] * sa + elb[0];
        s_obsdot = sb;
    }
    __syncthreads();

    // warp-per-row gather + 3 dots
    int r    = b * 8 + (tid >> 5);
    int lane = tid & 31;
    int cid  = __ldg(cids + r);
    const float4* e4 = (const float4*)(emb + (size_t)cid * 256);
    const float4* a4 = (const float4*)we1;
    const float4* b4 = (const float4*)wt0s;
    const float4* c4 = (const float4*)wt1s;
    float de = 0.f, du = 0.f, dv = 0.f;
    #pragma unroll
    for (int q = 0; q < 2; q++) {
        int i = lane * 2 + q;
        float4 x = e4[i];
        float4 a = a4[i], bb = b4[i], c = c4[i];
        de = fmaf(x.x,a.x, fmaf(x.y,a.y, fmaf(x.z,a.z, fmaf(x.w,a.w, de))));
        du = fmaf(x.x,bb.x,fmaf(x.y,bb.y,fmaf(x.z,bb.z,fmaf(x.w,bb.w,du))));
        dv = fmaf(x.x,c.x, fmaf(x.y,c.y, fmaf(x.z,c.z, fmaf(x.w,c.w, dv))));
    }
    #pragma unroll
    for (int o = 16; o; o >>= 1) {
        de += __shfl_xor_sync(0xffffffffu, de, o);
        du += __shfl_xor_sync(0xffffffffu, du, o);
        dv += __shfl_xor_sync(0xffffffffu, dv, o);
    }
    if (lane == 0) {
        float x = de + s_obsdot + s_ce;
        g_emit[r] = __fdividef(1.f, 1.f + __expf(-x));
        g_u[r] = du;
        g_v[r] = dv;
    }
}

// ============================================================
// K2 (fused A): build 4 leaves in smem + radix-4 product -> bufB[b]
// Leaf t<1023: M[j][k] = exp(sig(u[t][j]+v[t+1][k]+ct) + em[t+1][k] + (t==0?emit0[j]:0))
// Leaf 1023: identity.
// Dynamic smem: Apad(4160) + Bden(4096) + Ppad(4160) + Pden(4096) floats = 66048 B
// ============================================================
__device__ __forceinline__ void gemm64_256(const float* __restrict__ Ap,
                                           const float* __restrict__ Bd,
                                           float acc[4][4], int tid)
{
    int tx = tid & 15, ty = tid >> 4;
    const float4* B4 = (const float4*)Bd;
    #pragma unroll
    for (int r = 0; r < 4; r++)
        #pragma unroll
        for (int c = 0; c < 4; c++) acc[r][c] = 0.f;
    #pragma unroll 4
    for (int m = 0; m < 64; m++) {
        float4 bv = B4[m * 16 + tx];
        #pragma unroll
        for (int r = 0; r < 4; r++) {
            float av = Ap[(ty * 4 + r) * 65 + m];
            acc[r][0] = fmaf(av, bv.x, acc[r][0]);
            acc[r][1] = fmaf(av, bv.y, acc[r][1]);
            acc[r][2] = fmaf(av, bv.z, acc[r][2]);
            acc[r][3] = fmaf(av, bv.w, acc[r][3]);
        }
    }
}

__global__ __launch_bounds__(256) void fusedA_kernel(
    const float* __restrict__ tcb, const float* __restrict__ tlw,
    const float* __restrict__ tlb)
{
    extern __shared__ float dsm[];
    float* Apad = dsm;            // 4160
    float* Bden = dsm + 4160;     // 4096
    float* Ppad = dsm + 8256;     // 4160
    float* Pden = dsm + 12416;    // 4096

    __shared__ float u_s[64], v_s[64], em_s[64], e0_s[64];
    __shared__ float redc[8];
    __shared__ float s_ct, s_max;

    int tid = threadIdx.x, b = blockIdx.x;

    // ct = tcb * sum(tlw) + tlb  (per-block recompute)
    float tv = tlw[tid];
    #pragma unroll
    for (int o = 16; o; o >>= 1) tv += __shfl_xor_sync(0xffffffffu, tv, o);
    if ((tid & 31) == 0) redc[tid >> 5] = tv;
    __syncthreads();
    if (tid == 0) {
        float s = 0.f;
        #pragma unroll
        for (int i = 0; i < 8; i++) s += redc[i];
        s_ct = tcb[0] * s + tlb[0];
    }
    __syncthreads();
    float ct = s_ct;

    // ---- leaf builder (into dst with given row stride) ----
    auto build = [&](int t, float* dst, int stride) {
        if (t < TT - 1) {
            if (tid < 64) {
                u_s[tid]  = g_u[t * 64 + tid];
                v_s[tid]  = g_v[(t + 1) * 64 + tid];
                em_s[tid] = g_emit[(t + 1) * 64 + tid];
                e0_s[tid] = (t == 0) ? g_emit[tid] : 0.f;
            }
            __syncthreads();
            #pragma unroll
            for (int i = 0; i < 16; i++) {
                int idx = tid + i * 256;
                int j = idx >> 6, k = idx & 63;
                float x = u_s[j] + v_s[k] + ct;
                float s = __fdividef(1.f, 1.f + __expf(-x));
                dst[j * stride + k] = __expf(s + em_s[k] + e0_s[j]);
            }
            __syncthreads();
        } else {   // identity pad (t == 1023)
            __syncthreads();
            #pragma unroll
            for (int i = 0; i < 16; i++) {
                int idx = tid + i * 256;
                int j = idx >> 6, k = idx & 63;
                dst[j * stride + k] = (j == k) ? 1.f : 0.f;
            }
            __syncthreads();
        }
    };

    int t0 = 4 * b;
    float acc[4][4];
    int tx = tid & 15, ty = tid >> 4;

    build(t0 + 0, Apad, 65);
    build(t0 + 1, Bden, 64);
    gemm64_256(Apad, Bden, acc, tid);                 // P0 = M0*M1
    #pragma unroll
    for (int r = 0; r < 4; r++)
        #pragma unroll
        for (int c = 0; c < 4; c++)
            Ppad[(ty * 4 + r) * 65 + tx * 4 + c] = acc[r][c];
    __syncthreads();

    build(t0 + 2, Apad, 65);
    build(t0 + 3, Bden, 64);
    gemm64_256(Apad, Bden, acc, tid);                 // P1 = M2*M3
    float4* P4 = (float4*)Pden;
    #pragma unroll
    for (int r = 0; r < 4; r++)
        P4[(ty * 4 + r) * 16 + tx] =
            make_float4(acc[r][0], acc[r][1], acc[r][2], acc[r][3]);
    __syncthreads();

    gemm64_256(Ppad, Pden, acc, tid);                 // out = P0*P1

    // block max rescale
    float mx = acc[0][0];
    #pragma unroll
    for (int r = 0; r < 4; r++)
        #pragma unroll
        for (int c = 0; c < 4; c++) mx = fmaxf(mx, acc[r][c]);
    #pragma unroll
    for (int o = 16; o; o >>= 1) mx = fmaxf(mx, __shfl_xor_sync(0xffffffffu, mx, o));
    if ((tid & 31) == 0) redc[tid >> 5] = mx;
    __syncthreads();
    if (tid == 0) {
        float m = redc[0];
        #pragma unroll
        for (int i = 1; i < 8; i++) m = fmaxf(m, redc[i]);
        s_max = m;
        g_scB[b] = logf(m);
    }
    __syncthreads();
    float inv = __fdividef(1.f, s_max);

    float4* O4 = (float4*)(g_bufB + (size_t)b * 4096);
    #pragma unroll
    for (int r = 0; r < 4; r++)
        O4[(ty * 4 + r) * 16 + tx] =
            make_float4(acc[r][0]*inv, acc[r][1]*inv, acc[r][2]*inv, acc[r][3]*inv);
}

// ============================================================
// K3: one radix-2 tree level (max-rescaled). lvl&1: bufB->bufA, else bufA->bufB
// ============================================================
__global__ __launch_bounds__(128) void matprod(int lvl)
{
    const float* in  = (lvl & 1) ? g_bufB : g_bufA;
    float*       out = (lvl & 1) ? g_bufA : g_bufB;
    const float* sIn = (lvl & 1) ? g_scB  : g_scA;
    float*       sOut= (lvl & 1) ? g_scA  : g_scB;

    int b = blockIdx.x;
    const float4* A4 = (const float4*)(in + (size_t)(2 * b) * 4096);
    const float4* B4 = A4 + 1024;

    __shared__ float  As[64 * 65];
    __shared__ float4 Bs4[64 * 16];

    int tid = threadIdx.x;
    #pragma unroll
    for (int g = 0; g < 8; g++) {
        int p = tid + g * 128;
        float4 a = A4[p];
        int j = p >> 4, m4 = (p & 15) << 2;
        As[j * 65 + m4 + 0] = a.x;
        As[j * 65 + m4 + 1] = a.y;
        As[j * 65 + m4 + 2] = a.z;
        As[j * 65 + m4 + 3] = a.w;
        Bs4[p] = B4[p];
    }
    __syncthreads();

    int tx = tid & 15, ty = tid >> 4;
    const float* Ab = As + (size_t)ty * 8 * 65;

    float acc[8][4];
    #pragma unroll
    for (int r = 0; r < 8; r++)
        #pragma unroll
        for (int c = 0; c < 4; c++) acc[r][c] = 0.f;

    #pragma unroll 4
    for (int m = 0; m < 64; m++) {
        float4 bv = Bs4[m * 16 + tx];
        #pragma unroll
        for (int r = 0; r < 8; r++) {
            float av = Ab[r * 65 + m];
            acc[r][0] = fmaf(av, bv.x, acc[r][0]);
            acc[r][1] = fmaf(av, bv.y, acc[r][1]);
            acc[r][2] = fmaf(av, bv.z, acc[r][2]);
            acc[r][3] = fmaf(av, bv.w, acc[r][3]);
        }
    }

    float mx = acc[0][0];
    #pragma unroll
    for (int r = 0; r < 8; r++)
        #pragma unroll
        for (int c = 0; c < 4; c++) mx = fmaxf(mx, acc[r][c]);
    #pragma unroll
    for (int o = 16; o; o >>= 1) mx = fmaxf(mx, __shfl_xor_sync(0xffffffffu, mx, o));
    __shared__ float wm[4];
    if ((tid & 31) == 0) wm[tid >> 5] = mx;
    __syncthreads();
    float bm = fmaxf(fmaxf(wm[0], wm[1]), fmaxf(wm[2], wm[3]));
    float inv = __fdividef(1.f, bm);

    float4* O4 = (float4*)(out + (size_t)b * 4096);
    #pragma unroll
    for (int r = 0; r < 8; r++)
        O4[(ty * 8 + r) * 16 + tx] =
            make_float4(acc[r][0]*inv, acc[r][1]*inv, acc[r][2]*inv, acc[r][3]*inv);

    if (tid == 0) sOut[b] = sIn[2 * b] + sIn[2 * b + 1] + logf(bm);
}

// ============================================================
// K4: tail 64->1 in ONE kernel: 32 co-resident blocks + global spin barrier.
// Fixed /64 rescale per product (deterministic, no cross-block reduction);
// scale contribution = 63 * ln(64). Cross-SM data via L2 (__ldcg + fence).
// ============================================================
__device__ __forceinline__ void gbar(int p, int tid)
{
    __syncthreads();
    if (tid == 0) {
        __threadfence();
        atomicAdd((unsigned*)&g_cnt[p], 1u);
        while (g_cnt[p] < 32u) { }
    }
    __syncthreads();
}

template <int NC>
__device__ __forceinline__ void tail_gemm(const float* __restrict__ Ag,
                                          const float* __restrict__ Bg,
                                          float* __restrict__ Cg, int col0,
                                          float* sA, float* sB, int tid)
{
    const float4* Ag4 = (const float4*)Ag;
    #pragma unroll
    for (int g = 0; g < 4; g++) {
        int p = tid + g * 256;
        float4 a = __ldcg(Ag4 + p);
        int j = p >> 4, m4 = (p & 15) << 2;
        sA[j * 65 + m4 + 0] = a.x;
        sA[j * 65 + m4 + 1] = a.y;
        sA[j * 65 + m4 + 2] = a.z;
        sA[j * 65 + m4 + 3] = a.w;
    }
    constexpr int NC4 = NC / 4;
    const float4* Bg4 = (const float4*)Bg;
    float4* sB4 = (float4*)sB;
    for (int q = tid; q < 64 * NC4; q += 256) {
        int m = q / NC4, c = q - m * NC4;
        sB4[q] = __ldcg(Bg4 + m * 16 + (col0 >> 2) + c);
    }
    __syncthreads();

    constexpr int R = NC4 / 4;     // rows per thread (4/2/1)
    int tx = tid % NC4, ty = tid / NC4;
    float acc[R][4];
    #pragma unroll
    for (int r = 0; r < R; r++)
        #pragma unroll
        for (int c = 0; c < 4; c++) acc[r][c] = 0.f;

    #pragma unroll 4
    for (int m = 0; m < 64; m++) {
        float4 bv = sB4[m * NC4 + tx];
        #pragma unroll
        for (int r = 0; r < R; r++) {
            float av = sA[(ty * R + r) * 65 + m];
            acc[r][0] = fmaf(av, bv.x, acc[r][0]);
            acc[r][1] = fmaf(av, bv.y, acc[r][1]);
            acc[r][2] = fmaf(av, bv.z, acc[r][2]);
            acc[r][3] = fmaf(av, bv.w, acc[r][3]);
        }
    }
    const float inv = 1.f / 64.f;
    float4* Cg4 = (float4*)Cg;
    #pragma unroll
    for (int r = 0; r < R; r++)
        Cg4[(ty * R + r) * 16 + (col0 >> 2) + tx] =
            make_float4(acc[r][0]*inv, acc[r][1]*inv, acc[r][2]*inv, acc[r][3]*inv);
    __syncthreads();
}

__global__ __launch_bounds__(256) void tail_kernel(float* __restrict__ out)
{
    __shared__ __align__(16) float sA[64 * 65];
    __shared__ __align__(16) float sB[64 * 64];
    __shared__ float red[8];

    int b = blockIdx.x, tid = threadIdx.x;
    float* R0 = g_bufA;
    float* R1 = g_bufA + 32 * 4096;
    float* R2 = g_bufA + 48 * 4096;
    float* R3 = g_bufA + 56 * 4096;
    float* R4 = g_bufA + 60 * 4096;
    float* R5 = g_bufA + 62 * 4096;

    // p0: 64 -> 32 (1 block per GEMM)
    tail_gemm<64>(g_bufB + (size_t)(2*b)*4096, g_bufB + (size_t)(2*b+1)*4096,
                  R0 + (size_t)b*4096, 0, sA, sB, tid);
    gbar(0, tid);
    // p1: 32 -> 16 (2 blocks per GEMM, 32-col halves)
    { int g = b >> 1, c0 = (b & 1) * 32;
      tail_gemm<32>(R0 + (size_t)(2*g)*4096, R0 + (size_t)(2*g+1)*4096,
                    R1 + (size_t)g*4096, c0, sA, sB, tid); }
    gbar(1, tid);
    // p2: 16 -> 8 (4 blocks per GEMM, 16-col quarters)
    { int g = b >> 2, c0 = (b & 3) * 16;
      tail_gemm<16>(R1 + (size_t)(2*g)*4096, R1 + (size_t)(2*g+1)*4096,
                    R2 + (size_t)g*4096, c0, sA, sB, tid); }
    gbar(2, tid);
    // p3: 8 -> 4
    if (b < 16) { int g = b >> 2, c0 = (b & 3) * 16;
      tail_gemm<16>(R2 + (size_t)(2*g)*4096, R2 + (size_t)(2*g+1)*4096,
                    R3 + (size_t)g*4096, c0, sA, sB, tid); }
    gbar(3, tid);
    // p4: 4 -> 2
    if (b < 8) { int g = b >> 2, c0 = (b & 3) * 16;
      tail_gemm<16>(R3 + (size_t)(2*g)*4096, R3 + (size_t)(2*g+1)*4096,
                    R4 + (size_t)g*4096, c0, sA, sB, tid); }
    gbar(4, tid);
    // p5: 2 -> 1
    if (b < 4) { int c0 = b * 16;
      tail_gemm<16>(R4, R4 + 4096, R5, c0, sA, sB, tid); }
    gbar(5, tid);

    // final logZ
    if (b == 0) {
        float s = 0.f;
        for (int i = tid; i < 4096; i += 256) s += __ldcg(R5 + i);
        #pragma unroll
        for (int o = 16; o; o >>= 1) s += __shfl_xor_sync(0xffffffffu, s, o);
        if ((tid & 31) == 0) red[tid >> 5] = s;
        __syncthreads();
        if (tid == 0) {
            float sum = 0.f;
            #pragma unroll
            for (int i = 0; i < 8; i++) sum += red[i];
            float st = 0.f;
            for (int i = 0; i < 64; i++) st += g_scB[i];
            out[0] = logf(sum) + st + 63.f * 4.15888308335967f;  // 63*ln(64)
        }
    }
}

// ============================================================
extern "C" void kernel_launch(void* const* d_in, const int* in_sizes, int n_in,
                              void* d_out, int out_size)
{
    const float* obs = (const float*)d_in[0];
    const int*   cid = (const int*)  d_in[1];
    const float* emb = (const float*)d_in[2];
    const float* ecw = (const float*)d_in[3];
    const float* ecb = (const float*)d_in[4];
    const float* elw = (const float*)d_in[5];
    const float* elb = (const float*)d_in[6];
    const float* tcw = (const float*)d_in[7];
    const float* tcb = (const float*)d_in[8];
    const float* tlw = (const float*)d_in[9];
    const float* tlb = (const float*)d_in[10];
    float* out = (float*)d_out;

    static bool attr_set = false;
    if (!attr_set) {
        cudaFuncSetAttribute(fusedA_kernel,
                             cudaFuncAttributeMaxDynamicSharedMemorySize, 66048);
        attr_set = true;
    }

    gather_kernel<<<NT / 8, 256>>>(cid, emb, obs, ecw, ecb, elw, elb, tcw, tlw);
    fusedA_kernel<<<256, 256, 66048>>>(tcb, tlw, tlb);   // 1024 leaves -> 256
    matprod<<<128, 128>>>(1);                            // 256 -> 128 (B->A)
    matprod<<<64, 128>>>(0);                             // 128 -> 64  (A->B)
    tail_kernel<<<32, 256>>>(out);                       // 64 -> 1 + logZ
}

// round 4
// speedup vs baseline: 9.7830x; 1.0456x over previous
#include <cuda_runtime.h>

#define TT 1024
#define NT (TT*64)
#define NB 128
#define LN64 4.158883083359672f

// ---- device scratch (static only) ----
__device__ float g_u[NT], g_v[NT], g_emit[NT];
__device__ float g_bufA[NB * 4096];
__device__ float g_bufB[NB * 4096];
__device__ float g_sc[NB];
__device__ unsigned g_cnt[9];     // phase counters; self-resetting (zero at first launch)

// ============================================================
// Grid-wide spin barrier, phase p in [0,9). All NB blocks arrive.
// Last arriver resets slot (p-1 mod 9) -> safe across graph replays.
// ============================================================
__device__ __forceinline__ void gbar(int p, int tid)
{
    __syncthreads();
    if (tid == 0) {
        __threadfence();
        unsigned old = atomicAdd(&g_cnt[p], 1u);
        if (old == NB - 1u) {
            g_cnt[(p + 8) % 9] = 0u;
            __threadfence();
        }
        while (*((volatile unsigned*)&g_cnt[p]) < (unsigned)NB) { }
    }
    __syncthreads();
}

// ============================================================
// 64x64x64 GEMM, 256 threads: A padded (stride 65), B dense float4.
// ============================================================
__device__ __forceinline__ void gemm64_256(const float* __restrict__ Ap,
                                           const float* __restrict__ Bd,
                                           float acc[4][4], int tid)
{
    int tx = tid & 15, ty = tid >> 4;
    const float4* B4 = (const float4*)Bd;
    #pragma unroll
    for (int r = 0; r < 4; r++)
        #pragma unroll
        for (int c = 0; c < 4; c++) acc[r][c] = 0.f;
    #pragma unroll 4
    for (int m = 0; m < 64; m++) {
        float4 bv = B4[m * 16 + tx];
        #pragma unroll
        for (int r = 0; r < 4; r++) {
            float av = Ap[(ty * 4 + r) * 65 + m];
            acc[r][0] = fmaf(av, bv.x, acc[r][0]);
            acc[r][1] = fmaf(av, bv.y, acc[r][1]);
            acc[r][2] = fmaf(av, bv.z, acc[r][2]);
            acc[r][3] = fmaf(av, bv.w, acc[r][3]);
        }
    }
}

// ============================================================
// Column-split 64x64x NC GEMM with /64 rescale (tree levels).
// ============================================================
template <int NC>
__device__ __forceinline__ void tail_gemm(const float* __restrict__ Ag,
                                          const float* __restrict__ Bg,
                                          float* __restrict__ Cg, int col0,
                                          float* sA, float* sB, int tid)
{
    const float4* Ag4 = (const float4*)Ag;
    #pragma unroll
    for (int g = 0; g < 4; g++) {
        int p = tid + g * 256;
        float4 a = __ldcg(Ag4 + p);
        int j = p >> 4, m4 = (p & 15) << 2;
        sA[j * 65 + m4 + 0] = a.x;
        sA[j * 65 + m4 + 1] = a.y;
        sA[j * 65 + m4 + 2] = a.z;
        sA[j * 65 + m4 + 3] = a.w;
    }
    constexpr int NC4 = NC / 4;
    const float4* Bg4 = (const float4*)Bg;
    float4* sB4 = (float4*)sB;
    for (int q = tid; q < 64 * NC4; q += 256) {
        int m = q / NC4, c = q - m * NC4;
        sB4[q] = __ldcg(Bg4 + m * 16 + (col0 >> 2) + c);
    }
    __syncthreads();

    constexpr int R = NC4 / 4;     // rows per thread (2 for NC=32, 1 for NC=16)
    int tx = tid % NC4, ty = tid / NC4;
    float acc[R][4];
    #pragma unroll
    for (int r = 0; r < R; r++)
        #pragma unroll
        for (int c = 0; c < 4; c++) acc[r][c] = 0.f;

    #pragma unroll 4
    for (int m = 0; m < 64; m++) {
        float4 bv = sB4[m * NC4 + tx];
        #pragma unroll
        for (int r = 0; r < R; r++) {
            float av = sA[(ty * R + r) * 65 + m];
            acc[r][0] = fmaf(av, bv.x, acc[r][0]);
            acc[r][1] = fmaf(av, bv.y, acc[r][1]);
            acc[r][2] = fmaf(av, bv.z, acc[r][2]);
            acc[r][3] = fmaf(av, bv.w, acc[r][3]);
        }
    }
    const float inv = 1.f / 64.f;
    float4* Cg4 = (float4*)Cg;
    #pragma unroll
    for (int r = 0; r < R; r++)
        Cg4[(ty * R + r) * 16 + (col0 >> 2) + tx] =
            make_float4(acc[r][0]*inv, acc[r][1]*inv, acc[r][2]*inv, acc[r][3]*inv);
}

// ============================================================
// THE kernel: gather -> radix-8 leaf fold -> 7 tree levels -> logZ
// grid = 128 blocks x 256 threads (co-resident unconditionally)
// ============================================================
__global__ __launch_bounds__(256) void mono_kernel(
    const float* __restrict__ obs,  const int* __restrict__ cids,
    const float* __restrict__ emb,
    const float* __restrict__ ecw,  const float* __restrict__ ecb,
    const float* __restrict__ elw,  const float* __restrict__ elb,
    const float* __restrict__ tcw,  const float* __restrict__ tcb,
    const float* __restrict__ tlw,  const float* __restrict__ tlb,
    float* __restrict__ out)
{
    __shared__ __align__(16) float SM[8320];   // carved per phase (33.3 KB)
    __shared__ float u_s[64], v_s[64], em_s[64], e0_s[64];
    __shared__ float red[8];
    __shared__ float s_scalar;

    int tid  = threadIdx.x, b = blockIdx.x;
    int lane = tid & 31, w = tid >> 5;

    //================ P0: gather + folded prep ================
    {
        float* we0 = SM;
        float* we1 = SM + 256;
        float* wt0 = SM + 512;
        float* wt1 = SM + 768;
        int d = tid;
        float em1 = (d > 0)   ? elw[d-1] : 0.f;
        float e0v = elw[d];
        float ep1 = (d < 255) ? elw[d+1] : 0.f;
        we0[d] = ecw[0]*ep1 + ecw[1]*e0v + ecw[2]*em1;
        we1[d] = ecw[3]*ep1 + ecw[4]*e0v + ecw[5]*em1;
        float tm1 = (d > 0)   ? tlw[d-1] : 0.f;
        float t0v = tlw[d];
        float tp1 = (d < 255) ? tlw[d+1] : 0.f;
        wt0[d] = tcw[0]*tp1 + tcw[1]*t0v + tcw[2]*tm1;
        wt1[d] = tcw[3]*tp1 + tcw[4]*t0v + tcw[5]*tm1;

        float vs = e0v;
        #pragma unroll
        for (int o = 16; o; o >>= 1) vs += __shfl_xor_sync(0xffffffffu, vs, o);
        if (lane == 0) red[w] = vs;
        __syncthreads();
        if (tid == 0) {
            float s = 0.f;
            #pragma unroll
            for (int i = 0; i < 8; i++) s += red[i];
            s_scalar = ecb[0] * s + elb[0];
        }
        __syncthreads();
        float ce = s_scalar;

        int t = b * 8 + w;                      // one t per warp
        float od = 0.f;
        #pragma unroll
        for (int q = 0; q < 8; q++)
            od += obs[t * 256 + lane + q * 32] * we0[lane + q * 32];
        #pragma unroll
        for (int o = 16; o; o >>= 1) od += __shfl_xor_sync(0xffffffffu, od, o);

        const float4* A4 = (const float4*)we1;
        const float4* B4 = (const float4*)wt0;
        const float4* C4 = (const float4*)wt1;
        float4 a0 = A4[lane*2], a1 = A4[lane*2+1];
        float4 b0 = B4[lane*2], b1 = B4[lane*2+1];
        float4 c0 = C4[lane*2], c1 = C4[lane*2+1];

        for (int i = 0; i < 64; i += 4) {
            int r = t * 64 + i;
            int cid[4];
            #pragma unroll
            for (int j = 0; j < 4; j++) cid[j] = __ldg(cids + r + j);
            float4 x[4][2];
            #pragma unroll
            for (int j = 0; j < 4; j++) {
                const float4* e4 = (const float4*)(emb + (size_t)cid[j] * 256);
                x[j][0] = __ldg(e4 + lane * 2);
                x[j][1] = __ldg(e4 + lane * 2 + 1);
            }
            float de[4], du[4], dv[4];
            #pragma unroll
            for (int j = 0; j < 4; j++) {
                float4 p = x[j][0], q = x[j][1];
                de[j] = p.x*a0.x + p.y*a0.y + p.z*a0.z + p.w*a0.w
                      + q.x*a1.x + q.y*a1.y + q.z*a1.z + q.w*a1.w;
                du[j] = p.x*b0.x + p.y*b0.y + p.z*b0.z + p.w*b0.w
                      + q.x*b1.x + q.y*b1.y + q.z*b1.z + q.w*b1.w;
                dv[j] = p.x*c0.x + p.y*c0.y + p.z*c0.z + p.w*c0.w
                      + q.x*c1.x + q.y*c1.y + q.z*c1.z + q.w*c1.w;
            }
            #pragma unroll
            for (int j = 0; j < 4; j++) {
                #pragma unroll
                for (int o = 16; o; o >>= 1) {
                    de[j] += __shfl_xor_sync(0xffffffffu, de[j], o);
                    du[j] += __shfl_xor_sync(0xffffffffu, du[j], o);
                    dv[j] += __shfl_xor_sync(0xffffffffu, dv[j], o);
                }
            }
            #pragma unroll
            for (int j = 0; j < 4; j++) {
                if (lane == j) {
                    float xx = de[j] + od + ce;
                    g_emit[r + j] = __fdividef(1.f, 1.f + __expf(-xx));
                    g_u[r + j] = du[j];
                    g_v[r + j] = dv[j];
                }
            }
        }
    }
    gbar(0, tid);

    //================ P1: 8 leaves -> left-fold product ================
    {
        float tv = __ldg(tlw + tid);
        #pragma unroll
        for (int o = 16; o; o >>= 1) tv += __shfl_xor_sync(0xffffffffu, tv, o);
        if (lane == 0) red[w] = tv;
        __syncthreads();
        if (tid == 0) {
            float s = 0.f;
            #pragma unroll
            for (int i = 0; i < 8; i++) s += red[i];
            s_scalar = tcb[0] * s + tlb[0];
        }
        __syncthreads();
        float ct = s_scalar;

        float* Ppad = SM;          // 4160 floats, stride 65
        float* Mden = SM + 4160;   // 4096 floats, dense

        auto build = [&](int t, float* dst, int stride) {
            if (tid < 64) {
                u_s[tid]  = __ldcg(g_u + t * 64 + tid);
                v_s[tid]  = __ldcg(g_v + (t + 1) * 64 + tid);
                em_s[tid] = __ldcg(g_emit + (t + 1) * 64 + tid);
                e0_s[tid] = (t == 0) ? __ldcg(g_emit + tid) : 0.f;
            }
            __syncthreads();
            #pragma unroll
            for (int i = 0; i < 16; i++) {
                int idx = tid + i * 256;
                int j = idx >> 6, k = idx & 63;
                float xx = u_s[j] + v_s[k] + ct;
                float sg = __fdividef(1.f, 1.f + __expf(-xx));
                dst[j * stride + k] = __expf(sg + em_s[k] + e0_s[j]);
            }
            __syncthreads();
        };

        int t0 = 8 * b;
        build(t0, Ppad, 65);
        int tx = tid & 15, ty = tid >> 4;
        for (int s = 1; s < 8; s++) {
            int t = t0 + s;
            if (t >= TT - 1) break;          // identity tail (block 127)
            build(t, Mden, 64);
            float acc[4][4];
            gemm64_256(Ppad, Mden, acc, tid);
            __syncthreads();
            #pragma unroll
            for (int r = 0; r < 4; r++)
                #pragma unroll
                for (int c = 0; c < 4; c++)
                    Ppad[(ty * 4 + r) * 65 + tx * 4 + c] = acc[r][c];
            __syncthreads();
        }

        // block-max rescale -> g_bufB[b]
        float mx = 0.f;
        #pragma unroll
        for (int i = 0; i < 16; i++) {
            int idx = tid + i * 256;
            mx = fmaxf(mx, Ppad[(idx >> 6) * 65 + (idx & 63)]);
        }
        #pragma unroll
        for (int o = 16; o; o >>= 1) mx = fmaxf(mx, __shfl_xor_sync(0xffffffffu, mx, o));
        if (lane == 0) red[w] = mx;
        __syncthreads();
        if (tid == 0) {
            float m = red[0];
            #pragma unroll
            for (int i = 1; i < 8; i++) m = fmaxf(m, red[i]);
            s_scalar = m;
            g_sc[b] = logf(m);
        }
        __syncthreads();
        float inv = __fdividef(1.f, s_scalar);
        #pragma unroll
        for (int i = 0; i < 16; i++) {
            int idx = tid + i * 256;
            g_bufB[(size_t)b * 4096 + idx] =
                Ppad[(idx >> 6) * 65 + (idx & 63)] * inv;
        }
    }
    gbar(1, tid);

    float* sA = SM;
    float* sB = SM + 4160;

    // L2: 128 -> 64  (2 blocks/product, 32-col halves)   B -> A
    { int g = b >> 1, c0 = (b & 1) * 32;
      tail_gemm<32>(g_bufB + (size_t)(2*g)*4096, g_bufB + (size_t)(2*g+1)*4096,
                    g_bufA + (size_t)g*4096, c0, sA, sB, tid); }
    gbar(2, tid);
    // L3: 64 -> 32  (4 blocks/product, 16-col)           A -> B
    { int g = b >> 2, c0 = (b & 3) * 16;
      tail_gemm<16>(g_bufA + (size_t)(2*g)*4096, g_bufA + (size_t)(2*g+1)*4096,
                    g_bufB + (size_t)g*4096, c0, sA, sB, tid); }
    gbar(3, tid);
    // L4: 32 -> 16 (64 active)                            B -> A
    if (b < 64) { int g = b >> 2, c0 = (b & 3) * 16;
      tail_gemm<16>(g_bufB + (size_t)(2*g)*4096, g_bufB + (size_t)(2*g+1)*4096,
                    g_bufA + (size_t)g*4096, c0, sA, sB, tid); }
    gbar(4, tid);
    // L5: 16 -> 8 (32 active)                             A -> B
    if (b < 32) { int g = b >> 2, c0 = (b & 3) * 16;
      tail_gemm<16>(g_bufA + (size_t)(2*g)*4096, g_bufA + (size_t)(2*g+1)*4096,
                    g_bufB + (size_t)g*4096, c0, sA, sB, tid); }
    gbar(5, tid);
    // L6: 8 -> 4 (16 active)                              B -> A
    if (b < 16) { int g = b >> 2, c0 = (b & 3) * 16;
      tail_gemm<16>(g_bufB + (size_t)(2*g)*4096, g_bufB + (size_t)(2*g+1)*4096,
                    g_bufA + (size_t)g*4096, c0, sA, sB, tid); }
    gbar(6, tid);
    // L7: 4 -> 2 (8 active)                               A -> B
    if (b < 8) { int g = b >> 2, c0 = (b & 3) * 16;
      tail_gemm<16>(g_bufA + (size_t)(2*g)*4096, g_bufA + (size_t)(2*g+1)*4096,
                    g_bufB + (size_t)g*4096, c0, sA, sB, tid); }
    gbar(7, tid);
    // L8: 2 -> 1 (4 active)                               B -> A
    if (b < 4) { int c0 = b * 16;
      tail_gemm<16>(g_bufB, g_bufB + 4096, g_bufA, c0, sA, sB, tid); }
    gbar(8, tid);

    //================ final: logZ ================
    if (b == 0) {
        float s = 0.f;
        for (int i = tid; i < 4096; i += 256) s += __ldcg(g_bufA + i);
        #pragma unroll
        for (int o = 16; o; o >>= 1) s += __shfl_xor_sync(0xffffffffu, s, o);
        if (lane == 0) red[w] = s;
        __syncthreads();
        float sc = (tid < NB) ? __ldcg(g_sc + tid) : 0.f;
        #pragma unroll
        for (int o = 16; o; o >>= 1) sc += __shfl_xor_sync(0xffffffffu, sc, o);
        __shared__ float red2[8];
        if (lane == 0) red2[w] = sc;
        __syncthreads();
        if (tid == 0) {
            float tot = 0.f, scs = 0.f;
            #pragma unroll
            for (int i = 0; i < 8; i++) { tot += red[i]; scs += red2[i]; }
            out[0] = logf(tot) + scs + 127.f * LN64;
        }
    }
}

// ============================================================
extern "C" void kernel_launch(void* const* d_in, const int* in_sizes, int n_in,
                              void* d_out, int out_size)
{
    const float* obs = (const float*)d_in[0];
    const int*   cid = (const int*)  d_in[1];
    const float* emb = (const float*)d_in[2];
    const float* ecw = (const float*)d_in[3];
    const float* ecb = (const float*)d_in[4];
    const float* elw = (const float*)d_in[5];
    const float* elb = (const float*)d_in[6];
    const float* tcw = (const float*)d_in[7];
    const float* tcb = (const float*)d_in[8];
    const float* tlw = (const float*)d_in[9];
    const float* tlb = (const float*)d_in[10];
    float* out = (float*)d_out;

    mono_kernel<<<NB, 256>>>(obs, cid, emb, ecw, ecb, elw, elb,
                             tcw, tcb, tlw, tlb, out);
}